// round 12
// baseline (speedup 1.0000x reference)
#include <cuda_runtime.h>

// CritiGraph_64175401337324 — fused kernel v8:
//  v7 decoupled-warps body + phase-4 register diet (rn pipelined, w via LDS,
//  shift-trick dtype loads) + __launch_bounds__(256,5) for 40 warps/SM.

namespace {
constexpr int T_   = 1024;
constexpr int S_   = 64;
constexpr int D_   = 256;
constexpr int TP_  = 8;
constexpr int C_   = 65;
constexpr int CUR_TP_ = 4;
}

// pack |v| with sign in bit 31
__device__ __forceinline__ unsigned enc_loc(int v) {
    unsigned a = (unsigned)(v < 0 ? -v : v);
    if (v < 0) a |= 0x80000000u;
    return a;
}

// sign * (16 - e), e = frexp-exponent of ((|a|^|b|)+1). Exact in fp32.
__device__ __forceinline__ float cos_core(unsigned ea, unsigned eb) {
    unsigned u = ea ^ eb;
    int e = 32 - __clz((int)((u & 0x7FFFFFFFu) + 1u));
    float f = (float)(16 - e);
    return (u & 0x80000000u) ? -f : f;
}

__device__ __forceinline__ unsigned bfind_u32(unsigned x) {
    unsigned r;
    asm("bfind.u32 %0, %1;" : "=r"(r) : "r"(x));
    return r;                              // = 31 - clz(x), x != 0
}

// dtype-agnostic int load: element idx from base with elem size 4<<0 / 8 (LE low word)
__device__ __forceinline__ int ld_i(const char* base, int idx, int shf) {
    return *(const int*)(base + ((size_t)idx << shf));
}

__global__ void __launch_bounds__(256, 5) fused_kernel(
    const void*  __restrict__ sta_loc,
    const void*  __restrict__ nei_loc,
    const void*  __restrict__ rand_numbers,
    const float* __restrict__ sta_emb,
    const float* __restrict__ nei_emb,
    const float* __restrict__ mask,
    const float* __restrict__ rand_vals,
    const float* __restrict__ t_rand,
    float* __restrict__ out)
{
    const int t    = blockIdx.x;
    const int tid  = threadIdx.x;
    const int lane = tid & 31;
    const int warp = tid >> 5;

    __shared__ __align__(16) unsigned sh_ne[TP_][72];   // warp-private [w][s*9+p]
    __shared__ __align__(16) float    sh_G[TP_][72];
    __shared__ float    sh_w[TP_][TP_];                 // [w][s_local]
    __shared__ float    sh_wb2[TP_][TP_];               // [w][p]
    __shared__ float    sP1[TP_ * 264];                 // [w][j(33)][p]
    __shared__ float    sP2[TP_ * 264];
    __shared__ float    s_loss[C_ * TP_];
    __shared__ float    s_rv[TP_], s_rl[TP_];
    __shared__ int      s_sel;

    // ================= phase A: all loads issued up front =================
    const float4* st4 = (const float4*)(sta_emb + (size_t)t * D_);
    const float4  ua  = st4[lane];
    const float4  ub  = st4[lane + 32];
    const float4* nb  = (const float4*)(nei_emb + ((size_t)(t * S_ + warp * 8)) * D_);

    float4 A[4], Bv[4];
    #pragma unroll
    for (int r = 0; r < 4; ++r) {
        A[r]  = nb[r * 64 + lane];
        Bv[r] = nb[r * 64 + lane + 32];
    }

    // dtype probes (same 64 leading words for every CTA -> cache-hot)
    const long long* pw = (const long long*)sta_loc;
    long long dv0 = pw[lane * 2];
    long long dv1 = pw[lane * 2 + 1];

    // nei_loc slice, speculative both-dtype loads (consecutive int32 pair)
    const int sl = lane >> 2;                // s_local 0..7
    const int p0 = (lane & 3) * 2;           // p pair {p0, p0+1}
    long long nlA = ((const long long*)nei_loc)[(size_t)t * 512 + warp * 64 + lane * 2];
    long long nlB = ((const long long*)nei_loc)[(size_t)t * 512 + warp * 64 + lane * 2 + 1];
    long long nl32 = ((const long long*)nei_loc)[(size_t)t * 256 + warp * 32 + lane];

    // sta_loc pair for (p0, p0+1)
    long long oA  = ((const long long*)sta_loc)[(size_t)t * 8 + p0];
    long long oB  = ((const long long*)sta_loc)[(size_t)t * 8 + p0 + 1];
    long long o32 = ((const long long*)sta_loc)[(size_t)t * 4 + (lane & 3)];

    float m_a   = mask[t * S_ + lane];
    float m_b   = mask[t * S_ + 32 + lane];
    float m_own = mask[t * S_ + warp * 8 + sl];

    if (tid < TP_) s_rv[tid] = rand_vals[t * TP_ + tid];
    if (tid == 0)  s_sel = (t_rand[t] < 0.8f) ? 1 : 0;

    // dtype decision (per warp, no cross-warp sync)
    int is64;
    {
        int lo0 = (int)dv0, hi0 = (int)(dv0 >> 32);
        int lo1 = (int)dv1, hi1 = (int)(dv1 >> 32);
        int ok = (hi0 == (lo0 >> 31)) && (hi1 == (lo1 >> 31));
        is64 = (__ballot_sync(0xFFFFFFFFu, ok) == 0xFFFFFFFFu);
    }
    const int shf = is64 ? 3 : 2;
    const char* RNB = (const char*)rand_numbers + (((size_t)t * 256) << shf);
    const char* SLB = (const char*)sta_loc      + (((size_t)t * 8)   << shf);

    int nl0, nl1, o0, o1;
    if (is64) {
        nl0 = (int)nlA; nl1 = (int)nlB;
        o0  = (int)oA;  o1  = (int)oB;
    } else {
        nl0 = (int)nl32; nl1 = (int)(nl32 >> 32);
        o0  = (int)o32;  o1  = (int)(o32 >> 32);
    }

    // per-warp lth (mask is 0/1: exact in any order)
    float invlth;
    {
        float l = m_a + m_b;
        #pragma unroll
        for (int off = 16; off; off >>= 1) l += __shfl_xor_sync(0xFFFFFFFFu, l, off);
        invlth = __frcp_rn(l + 1e-12f);
    }

    // encode + cos_sn + A8 (warp-local column sums over p)
    float A8_0, A8_1;
    {
        unsigned ne0 = enc_loc(nl0);
        unsigned ne1 = enc_loc(nl1);
        float cs0 = cos_core(enc_loc(o0), ne0) * 0.0625f;   // exact cos
        float cs1 = cos_core(enc_loc(o1), ne1) * 0.0625f;
        float c01 = cs0 + cs1;
        float c2  = c01 + __shfl_xor_sync(0xFFFFFFFFu, c01, 1);
        float sum8 = c2 + __shfl_xor_sync(0xFFFFFFFFu, c2, 2);  // sum over 8 p
        A8_0 = (sum8 - cs0) * 0.125f;
        A8_1 = (sum8 - cs1) * 0.125f;
        sh_ne[warp][sl * 9 + p0]     = ne0;
        sh_ne[warp][sl * 9 + p0 + 1] = ne1;
    }

    // ================= eu: FFMA batch-1, load batch-2, FFMA batch-2 =======
    float dot[8], nn[8];
    #pragma unroll
    for (int r = 0; r < 4; ++r) {
        dot[r] = A[r].x*ua.x + A[r].y*ua.y + A[r].z*ua.z + A[r].w*ua.w
               + Bv[r].x*ub.x + Bv[r].y*ub.y + Bv[r].z*ub.z + Bv[r].w*ub.w;
        nn[r]  = A[r].x*A[r].x + A[r].y*A[r].y + A[r].z*A[r].z + A[r].w*A[r].w
               + Bv[r].x*Bv[r].x + Bv[r].y*Bv[r].y + Bv[r].z*Bv[r].z + Bv[r].w*Bv[r].w;
    }
    #pragma unroll
    for (int r = 0; r < 4; ++r) {
        A[r]  = nb[(4 + r) * 64 + lane];
        Bv[r] = nb[(4 + r) * 64 + lane + 32];
    }
    #pragma unroll
    for (int r = 0; r < 4; ++r) {
        dot[4+r] = A[r].x*ua.x + A[r].y*ua.y + A[r].z*ua.z + A[r].w*ua.w
                 + Bv[r].x*ub.x + Bv[r].y*ub.y + Bv[r].z*ub.z + Bv[r].w*ub.w;
        nn[4+r]  = A[r].x*A[r].x + A[r].y*A[r].y + A[r].z*A[r].z + A[r].w*A[r].w
                 + Bv[r].x*Bv[r].x + Bv[r].y*Bv[r].y + Bv[r].z*Bv[r].z + Bv[r].w*Bv[r].w;
    }
    float ss = ua.x*ua.x + ua.y*ua.y + ua.z*ua.z + ua.w*ua.w
             + ub.x*ub.x + ub.y*ub.y + ub.z*ub.z + ub.w*ub.w;

    float euv;   // valid at lanes 2*row (row 0..7)
    {
        float r16[16];
        #pragma unroll
        for (int i = 0; i < 8; ++i) { r16[i] = dot[i]; r16[8+i] = nn[i]; }
        float t0[16];
        #pragma unroll
        for (int i = 0; i < 16; ++i)
            t0[i] = r16[i] + __shfl_xor_sync(0xFFFFFFFFu, r16[i], 16);
        float m8[8];
        #pragma unroll
        for (int k = 0; k < 8; ++k) m8[k] = (lane & 16) ? t0[k+8] : t0[k];
        float u4[8];
        #pragma unroll
        for (int k = 0; k < 8; ++k)
            u4[k] = m8[k] + __shfl_xor_sync(0xFFFFFFFFu, m8[k], 8);
        float q[4];
        #pragma unroll
        for (int k = 0; k < 4; ++k) q[k] = (lane & 8) ? u4[k+4] : u4[k];
        float v4[4];
        #pragma unroll
        for (int k = 0; k < 4; ++k)
            v4[k] = q[k] + __shfl_xor_sync(0xFFFFFFFFu, q[k], 4);
        float w0 = (lane & 4) ? v4[2] : v4[0];
        float w1 = (lane & 4) ? v4[3] : v4[1];
        float x0 = w0 + __shfl_xor_sync(0xFFFFFFFFu, w0, 2);
        float x1 = w1 + __shfl_xor_sync(0xFFFFFFFFu, w1, 2);
        float y  = (lane & 2) ? x1 : x0;
        float z  = y + __shfl_xor_sync(0xFFFFFFFFu, y, 1);
        #pragma unroll
        for (int off = 16; off; off >>= 1) ss += __shfl_xor_sync(0xFFFFFFFFu, ss, off);
        float nnv = __shfl_xor_sync(0xFFFFFFFFu, z, 16);
        euv = z / (sqrtf(ss) * sqrtf(nnv));   // meaningful at even lanes <16
    }

    // ================= G-prep (warp-local) =================
    {
        float eu_s = __shfl_sync(0xFFFFFFFFu, euv, sl * 2);
        float w_s  = fabsf(eu_s) * m_own * invlth;
        float B0 = A8_0 - eu_s;
        float B1 = A8_1 - eu_s;
        float q0 = w_s * B0, q1 = w_s * B1;
        sh_G[warp][sl * 9 + p0]     = q0 + q0;     // 2wB (exact x2)
        sh_G[warp][sl * 9 + p0 + 1] = q1 + q1;
        if ((lane & 3) == 0) sh_w[warp][sl] = w_s;
        float wb2_0 = q0 * B0;
        float wb2_1 = q1 * B1;
        #pragma unroll
        for (int off = 4; off <= 16; off <<= 1) {     // sum over 8 s-lanes
            wb2_0 += __shfl_xor_sync(0xFFFFFFFFu, wb2_0, off);
            wb2_1 += __shfl_xor_sync(0xFFFFFFFFu, wb2_1, off);
        }
        if (lane < 4) {
            sh_wb2[warp][2 * lane]     = wb2_0;
            sh_wb2[warp][2 * lane + 1] = wb2_1;
        }
    }
    __syncwarp();

    // ================= phase 4: per-warp partials over own 8 s =============
    {
        const int p  = lane & 7;
        const int jj = lane >> 3;

        unsigned ne_r[8];
        float    G_r[8];
        #pragma unroll
        for (int s = 0; s < 8; ++s) {
            ne_r[s] = sh_ne[warp][s * 9 + p];
            G_r[s]  = sh_G[warp][s * 9 + p];
        }
        const float wb2p  = sh_wb2[warp][p];
        const int   ori_p = ld_i(SLB, p, shf);

#define PROC8(E0, P1, P2) do {                                                \
        _Pragma("unroll")                                                     \
        for (int s = 0; s < 8; ++s) {                                         \
            float wv = sh_w[warp][s];                                         \
            unsigned u  = (E0) ^ ne_r[s];                                     \
            unsigned x2 = u * 2u + 2u;                                        \
            float fc = __uint_as_float(0x4B000000u | bfind_u32(x2));          \
            float mg = __fmaf_rn(fc, -0.0078125f, 65536.125f);                \
            float sG = __uint_as_float(__float_as_uint(G_r[s]) ^              \
                                       (u & 0x80000000u));                    \
            P1 = __fmaf_rn(mg, sG, P1);                                       \
            P2 = __fmaf_rn(__fmul_rn(mg, mg), wv, P2);                        \
        }                                                                     \
    } while (0)

        // steps 0..7: candidate j = step*4 + jj, rn pipelined 1 ahead
        int rn_next = ld_i(RNB, jj * 8 + p, shf);
        #pragma unroll 1
        for (int step = 0; step < 8; ++step) {
            int rn_cur = rn_next;
            if (step < 7) rn_next = ld_i(RNB, ((step + 1) * 4 + jj) * 8 + p, shf);
            int j = step * 4 + jj;
            int h = j >> 1;
            int vc = (ori_p ^ (1 << h)) ^ (rn_cur & ((1 << h) - 1));
            unsigned e0 = enc_loc(vc);
            float P1 = 0.f, P2 = wb2p;
            PROC8(e0, P1, P2);
            int base = (warp * 33 + j) * 8 + p;
            sP1[base] = P1;
            sP2[base] = P2;
        }
        // candidate 32 (= ori); all jj compute identical values, jj==0 stores
        {
            unsigned e0 = enc_loc(ori_p);
            float P1 = 0.f, P2 = wb2p;
            PROC8(e0, P1, P2);
            if (jj == 0) {
                int base = (warp * 33 + 32) * 8 + p;
                sP1[base] = P1;
                sP2[base] = P2;
            }
        }
#undef PROC8
    }
    __syncthreads();

    // ================= phase 5a: reduce partials over warps ================
    {
        const int j_ = tid >> 3, p_ = tid & 7;
        float S1 = 0.f, S2 = 0.f;
        #pragma unroll
        for (int w = 0; w < 8; ++w) {
            S1 = __fadd_rn(S1, sP1[(w * 33 + j_) * 8 + p_]);
            S2 = __fadd_rn(S2, sP2[(w * 33 + j_) * 8 + p_]);
        }
        // flip bit: candidate value == 0 keeps '+' sign under negation
        int rnv = ld_i(RNB, j_ * 8 + p_, shf);
        int orv = ld_i(SLB, p_, shf);
        int h = j_ >> 1;
        int vc = (orv ^ (1 << h)) ^ (rnv & ((1 << h) - 1));
        unsigned flip = vc ? 0x80000000u : 0u;
        s_loss[j_ * 8 + p_]        = S2 + S1;
        s_loss[(j_ + 33) * 8 + p_] = S2 + __uint_as_float(__float_as_uint(S1) ^ flip);
        if (tid < TP_) {                     // candidate 32
            float T1 = 0.f, T2 = 0.f;
            #pragma unroll
            for (int w = 0; w < 8; ++w) {
                T1 = __fadd_rn(T1, sP1[(w * 33 + 32) * 8 + tid]);
                T2 = __fadd_rn(T2, sP2[(w * 33 + 32) * 8 + tid]);
            }
            s_loss[32 * 8 + tid] = T2 + T1;
        }
    }
    __syncthreads();

    // ================= phase 5b: warp p argmin + outputs ===================
    {
        const int p = warp;
        float va = s_loss[lane * 8 + p];
        float vb = s_loss[(lane + 33) * 8 + p];
        float v = va; int ci = lane;
        if (vb < v) { v = vb; ci = lane + 33; }
        if (lane == 0) {
            float v32 = s_loss[32 * 8 + p];
            if (v32 < v || (v32 == v && 32 < ci)) { v = v32; ci = 32; }
        }
        #pragma unroll
        for (int off = 16; off; off >>= 1) {
            float v2 = __shfl_xor_sync(0xFFFFFFFFu, v, off);
            int   c2 = __shfl_xor_sync(0xFFFFFFFFu, ci, off);
            if (v2 < v || (v2 == v && c2 < ci)) { v = v2; ci = c2; }
        }
        if (lane == 0) {
            float rp = s_rv[p];
            int rank = 0;
            #pragma unroll
            for (int q = 0; q < TP_; ++q)
                rank += (s_rv[q] < rp) || (s_rv[q] == rp && q < p);
            int idx = (rank < CUR_TP_ && s_sel) ? ci : 32;
            int orv = ld_i(SLB, p, shf);
            int vv;
            if (idx == 32) {
                vv = orv;
            } else {
                int c = (idx < 32) ? idx : (idx - 33);
                int rnv = ld_i(RNB, c * 8 + p, shf);
                int h = c >> 1;
                vv = (orv ^ (1 << h)) ^ (rnv & ((1 << h) - 1));
                if (idx >= 33) vv = -vv;
            }
            out[t * TP_ + p] = (float)vv;
            s_rl[p] = s_loss[idx * 8 + p];
        }
    }
    __syncthreads();
    if (tid == 0) {
        float rl = 0.f;
        #pragma unroll
        for (int p = 0; p < TP_; ++p) rl = __fadd_rn(rl, s_rl[p]);
        out[T_ * TP_ + t] = rl * 0.125f;
    }
}

extern "C" void kernel_launch(void* const* d_in, const int* in_sizes, int n_in,
                              void* d_out, int out_size) {
    (void)in_sizes; (void)n_in; (void)out_size;
    fused_kernel<<<T_, 256>>>(
        d_in[0], d_in[1], d_in[2],
        (const float*)d_in[3], (const float*)d_in[4], (const float*)d_in[5],
        (const float*)d_in[6], (const float*)d_in[7],
        (float*)d_out);
}

// round 14
// speedup vs baseline: 1.0639x; 1.0639x over previous
#include <cuda_runtime.h>

// CritiGraph_64175401337324 — fused kernel v9 "512-thread single-batch":
// 16 warps/CTA, each warp owns 4 s-rows end-to-end with ONE load batch
// (one DRAM stall window per warp instead of two). Decoupled warps as v7.

namespace {
constexpr int T_   = 1024;
constexpr int S_   = 64;
constexpr int D_   = 256;
constexpr int TP_  = 8;
constexpr int C_   = 65;
constexpr int CUR_TP_ = 4;
constexpr int W_   = 16;                  // warps per CTA
}

// pack |v| with sign in bit 31
__device__ __forceinline__ unsigned enc_loc(int v) {
    unsigned a = (unsigned)(v < 0 ? -v : v);
    if (v < 0) a |= 0x80000000u;
    return a;
}

// sign * (16 - e), e = frexp-exponent of ((|a|^|b|)+1). Exact in fp32.
__device__ __forceinline__ float cos_core(unsigned ea, unsigned eb) {
    unsigned u = ea ^ eb;
    int e = 32 - __clz((int)((u & 0x7FFFFFFFu) + 1u));
    float f = (float)(16 - e);
    return (u & 0x80000000u) ? -f : f;
}

__device__ __forceinline__ unsigned bfind_u32(unsigned x) {
    unsigned r;
    asm("bfind.u32 %0, %1;" : "=r"(r) : "r"(x));
    return r;                              // = 31 - clz(x), x != 0
}

// dtype-agnostic int load (LE low word of int32/int64 element)
__device__ __forceinline__ int ld_i(const char* base, int idx, int shf) {
    return *(const int*)(base + ((size_t)idx << shf));
}

__global__ void __launch_bounds__(512, 2) fused_kernel(
    const void*  __restrict__ sta_loc,
    const void*  __restrict__ nei_loc,
    const void*  __restrict__ rand_numbers,
    const float* __restrict__ sta_emb,
    const float* __restrict__ nei_emb,
    const float* __restrict__ mask,
    const float* __restrict__ rand_vals,
    const float* __restrict__ t_rand,
    float* __restrict__ out)
{
    const int t    = blockIdx.x;
    const int tid  = threadIdx.x;
    const int lane = tid & 31;
    const int warp = tid >> 5;

    __shared__ __align__(16) unsigned sh_ne[W_][36];    // [w][sl*9+p]
    __shared__ __align__(16) float    sh_G[W_][36];
    __shared__ float    sh_w[W_][4];                    // [w][sl]
    __shared__ float    sh_wb2[W_][TP_];                // [w][p]
    __shared__ float    sP1[W_ * 264];                  // [w][j(33)][p]
    __shared__ float    sP2[W_ * 264];
    __shared__ float    s_loss[C_ * TP_];
    __shared__ float    s_rv[TP_], s_rl[TP_];
    __shared__ int      s_sel;

    // ================= phase A: all loads issued up front =================
    const float4* st4 = (const float4*)(sta_emb + (size_t)t * D_);
    const float4  ua  = st4[lane];
    const float4  ub  = st4[lane + 32];
    const float4* nb  = (const float4*)(nei_emb + ((size_t)(t * S_ + warp * 4)) * D_);

    float4 A[4], Bv[4];                   // single batch: warp's 4 rows
    #pragma unroll
    for (int r = 0; r < 4; ++r) {
        A[r]  = nb[r * 64 + lane];
        Bv[r] = nb[r * 64 + lane + 32];
    }

    // dtype probes (same 64 leading words for every CTA -> cache-hot)
    const long long* pw = (const long long*)sta_loc;
    long long dv0 = pw[lane * 2];
    long long dv1 = pw[lane * 2 + 1];

    // lane = sl*8 + p covers this warp's 4 s-rows x 8 p
    const int sl = lane >> 3;                // s_local 0..3
    const int p  = lane & 7;
    const int li = t * 512 + warp * 32 + lane;       // nei_loc element idx
    long long nl64 = ((const long long*)nei_loc)[li];
    int       nl32v = ((const int*)nei_loc)[li];
    long long o64  = ((const long long*)sta_loc)[(size_t)t * 8 + p];
    int       o32v = ((const int*)sta_loc)[(size_t)t * 8 + p];

    float m_a   = mask[t * S_ + lane];
    float m_b   = mask[t * S_ + 32 + lane];
    float m_own = mask[t * S_ + warp * 4 + sl];

    if (tid < TP_) s_rv[tid] = rand_vals[t * TP_ + tid];
    if (tid == 0)  s_sel = (t_rand[t] < 0.8f) ? 1 : 0;

    // dtype decision (per warp, no cross-warp sync)
    int is64;
    {
        int lo0 = (int)dv0, hi0 = (int)(dv0 >> 32);
        int lo1 = (int)dv1, hi1 = (int)(dv1 >> 32);
        int ok = (hi0 == (lo0 >> 31)) && (hi1 == (lo1 >> 31));
        is64 = (__ballot_sync(0xFFFFFFFFu, ok) == 0xFFFFFFFFu);
    }
    const int shf = is64 ? 3 : 2;
    const char* RNB = (const char*)rand_numbers + (((size_t)t * 256) << shf);
    const char* SLB = (const char*)sta_loc      + (((size_t)t * 8)   << shf);

    const int nl = is64 ? (int)nl64 : nl32v;
    const int o0 = is64 ? (int)o64  : o32v;

    // per-warp lth (mask is 0/1: exact in any order)
    float invlth;
    {
        float l = m_a + m_b;
        #pragma unroll
        for (int off = 16; off; off >>= 1) l += __shfl_xor_sync(0xFFFFFFFFu, l, off);
        invlth = __frcp_rn(l + 1e-12f);
    }

    // encode + cos_sn + A8 (8-lane p-group sums; tree identical to v7's)
    float A8;
    {
        unsigned ne = enc_loc(nl);
        float cs = cos_core(enc_loc(o0), ne) * 0.0625f;   // exact cos
        float c = cs;
        c += __shfl_xor_sync(0xFFFFFFFFu, c, 1);
        c += __shfl_xor_sync(0xFFFFFFFFu, c, 2);
        c += __shfl_xor_sync(0xFFFFFFFFu, c, 4);          // sum over 8 p
        A8 = (c - cs) * 0.125f;
        sh_ne[warp][sl * 9 + p] = ne;
    }

    // ================= eu: dots for 4 rows, merged butterfly ==============
    float dot[4], nn[4];
    #pragma unroll
    for (int r = 0; r < 4; ++r) {
        dot[r] = A[r].x*ua.x + A[r].y*ua.y + A[r].z*ua.z + A[r].w*ua.w
               + Bv[r].x*ub.x + Bv[r].y*ub.y + Bv[r].z*ub.z + Bv[r].w*ub.w;
        nn[r]  = A[r].x*A[r].x + A[r].y*A[r].y + A[r].z*A[r].z + A[r].w*A[r].w
               + Bv[r].x*Bv[r].x + Bv[r].y*Bv[r].y + Bv[r].z*Bv[r].z + Bv[r].w*Bv[r].w;
    }
    float ss = ua.x*ua.x + ua.y*ua.y + ua.z*ua.z + ua.w*ua.w
             + ub.x*ub.x + ub.y*ub.y + ub.z*ub.z + ub.w*ub.w;

    float euv;   // valid at lanes with (lane&16)==0; row r = ((lane>>3)&1)*2+((lane>>2)&1)
    {
        float r8[8];
        #pragma unroll
        for (int i = 0; i < 4; ++i) { r8[i] = dot[i]; r8[4+i] = nn[i]; }
        float t0[8];
        #pragma unroll
        for (int i = 0; i < 8; ++i)
            t0[i] = r8[i] + __shfl_xor_sync(0xFFFFFFFFu, r8[i], 16);
        float m4[4];
        #pragma unroll
        for (int k = 0; k < 4; ++k) m4[k] = (lane & 16) ? t0[k+4] : t0[k];
        float u4[4];
        #pragma unroll
        for (int k = 0; k < 4; ++k)
            u4[k] = m4[k] + __shfl_xor_sync(0xFFFFFFFFu, m4[k], 8);
        float q2[2];
        q2[0] = (lane & 8) ? u4[2] : u4[0];
        q2[1] = (lane & 8) ? u4[3] : u4[1];
        float v2[2];
        #pragma unroll
        for (int k = 0; k < 2; ++k)
            v2[k] = q2[k] + __shfl_xor_sync(0xFFFFFFFFu, q2[k], 4);
        float y = (lane & 4) ? v2[1] : v2[0];
        float x = y + __shfl_xor_sync(0xFFFFFFFFu, y, 2);
        float z = x + __shfl_xor_sync(0xFFFFFFFFu, x, 1);
        #pragma unroll
        for (int off = 16; off; off >>= 1) ss += __shfl_xor_sync(0xFFFFFFFFu, ss, off);
        float nnv = __shfl_xor_sync(0xFFFFFFFFu, z, 16);   // nn of same row
        euv = z / (sqrtf(ss) * sqrtf(nnv));
    }

    // ================= G-prep (warp-local) =================
    {
        // row r lives at lane: bit3 = r bit1, bit2 = r bit0, bit4 = 0
        int src = ((sl & 2) << 2) | ((sl & 1) << 2);
        src = ((sl & 2) ? 8 : 0) | ((sl & 1) ? 4 : 0);
        float eu_s = __shfl_sync(0xFFFFFFFFu, euv, src);
        float w_s  = fabsf(eu_s) * m_own * invlth;
        float B = A8 - eu_s;
        float q = w_s * B;
        sh_G[warp][sl * 9 + p] = q + q;              // 2wB (exact x2)
        if (p == 0) sh_w[warp][sl] = w_s;
        // wb2 per p: sum over this warp's 4 sl, tree (sl0+sl1)+(sl2+sl3)
        float wb2 = q * B;
        wb2 += __shfl_xor_sync(0xFFFFFFFFu, wb2, 8);
        wb2 += __shfl_xor_sync(0xFFFFFFFFu, wb2, 16);
        if (lane < 8) sh_wb2[warp][p] = wb2;
    }
    __syncwarp();

    // ================= phase 4: per-warp partials over own 4 s =============
    {
        const int jj = lane >> 3;                    // 0..3

        unsigned ne_r[4];
        float    G_r[4], w_r[4];
        #pragma unroll
        for (int s = 0; s < 4; ++s) {
            ne_r[s] = sh_ne[warp][s * 9 + p];
            G_r[s]  = sh_G[warp][s * 9 + p];
            w_r[s]  = sh_w[warp][s];
        }
        const float wb2p  = sh_wb2[warp][p];
        const int   ori_p = ld_i(SLB, p, shf);

        int rn_r[8];
        #pragma unroll
        for (int k = 0; k < 8; ++k)
            rn_r[k] = ld_i(RNB, (k * 4 + jj) * 8 + p, shf);
        const unsigned e0_32 = enc_loc(ori_p);

        #pragma unroll
        for (int step = 0; step < 9; ++step) {
            unsigned e0;
            int j;
            if (step < 8) {
                j = step * 4 + jj;
                int h = j >> 1;
                int vc = (ori_p ^ (1 << h)) ^ (rn_r[step] & ((1 << h) - 1));
                e0 = enc_loc(vc);
            } else {
                j = 32;
                e0 = e0_32;
            }
            float P1 = 0.f, P2 = wb2p;
            #pragma unroll
            for (int s = 0; s < 4; ++s) {
                unsigned u  = e0 ^ ne_r[s];
                unsigned x2 = u * 2u + 2u;
                float fc = __uint_as_float(0x4B000000u | bfind_u32(x2));
                float mg = __fmaf_rn(fc, -0.0078125f, 65536.125f);
                float sG = __uint_as_float(__float_as_uint(G_r[s]) ^ (u & 0x80000000u));
                P1 = __fmaf_rn(mg, sG, P1);
                P2 = __fmaf_rn(__fmul_rn(mg, mg), w_r[s], P2);
            }
            if (step < 8 || jj == 0) {
                int base = (warp * 33 + j) * 8 + p;
                sP1[base] = P1;
                sP2[base] = P2;
            }
        }
    }
    __syncthreads();

    // ================= phase 5a: reduce partials over 16 warps =============
    if (tid < 264) {
        const int j_ = tid >> 3, p_ = tid & 7;       // j_ 0..32
        float S1 = 0.f, S2 = 0.f;
        #pragma unroll
        for (int w = 0; w < W_; ++w) {
            S1 = __fadd_rn(S1, sP1[(w * 33 + j_) * 8 + p_]);
            S2 = __fadd_rn(S2, sP2[(w * 33 + j_) * 8 + p_]);
        }
        if (j_ < 32) {
            int rnv = ld_i(RNB, j_ * 8 + p_, shf);
            int orv = ld_i(SLB, p_, shf);
            int h = j_ >> 1;
            int vc = (orv ^ (1 << h)) ^ (rnv & ((1 << h) - 1));
            unsigned flip = vc ? 0x80000000u : 0u;   // -0 keeps '+' sign
            s_loss[j_ * 8 + p_]        = S2 + S1;
            s_loss[(j_ + 33) * 8 + p_] = S2 + __uint_as_float(__float_as_uint(S1) ^ flip);
        } else {
            s_loss[32 * 8 + p_] = S2 + S1;
        }
    }
    __syncthreads();

    // ================= phase 5b: warp p argmin + outputs ===================
    if (warp < TP_) {
        const int pp = warp;
        float va = s_loss[lane * 8 + pp];
        float vb = s_loss[(lane + 33) * 8 + pp];
        float v = va; int ci = lane;
        if (vb < v) { v = vb; ci = lane + 33; }
        if (lane == 0) {
            float v32 = s_loss[32 * 8 + pp];
            if (v32 < v || (v32 == v && 32 < ci)) { v = v32; ci = 32; }
        }
        #pragma unroll
        for (int off = 16; off; off >>= 1) {
            float v2 = __shfl_xor_sync(0xFFFFFFFFu, v, off);
            int   c2 = __shfl_xor_sync(0xFFFFFFFFu, ci, off);
            if (v2 < v || (v2 == v && c2 < ci)) { v = v2; ci = c2; }
        }
        if (lane == 0) {
            float rp = s_rv[pp];
            int rank = 0;
            #pragma unroll
            for (int q = 0; q < TP_; ++q)
                rank += (s_rv[q] < rp) || (s_rv[q] == rp && q < pp);
            int idx = (rank < CUR_TP_ && s_sel) ? ci : 32;
            int orv = ld_i(SLB, pp, shf);
            int vv;
            if (idx == 32) {
                vv = orv;
            } else {
                int c = (idx < 32) ? idx : (idx - 33);
                int rnv = ld_i(RNB, c * 8 + pp, shf);
                int h = c >> 1;
                vv = (orv ^ (1 << h)) ^ (rnv & ((1 << h) - 1));
                if (idx >= 33) vv = -vv;
            }
            out[t * TP_ + pp] = (float)vv;
            s_rl[pp] = s_loss[idx * 8 + pp];
        }
    }
    __syncthreads();
    if (tid == 0) {
        float rl = 0.f;
        #pragma unroll
        for (int pq = 0; pq < TP_; ++pq) rl = __fadd_rn(rl, s_rl[pq]);
        out[T_ * TP_ + t] = rl * 0.125f;
    }
}

extern "C" void kernel_launch(void* const* d_in, const int* in_sizes, int n_in,
                              void* d_out, int out_size) {
    (void)in_sizes; (void)n_in; (void)out_size;
    fused_kernel<<<T_, 512>>>(
        d_in[0], d_in[1], d_in[2],
        (const float*)d_in[3], (const float*)d_in[4], (const float*)d_in[5],
        (const float*)d_in[6], (const float*)d_in[7],
        (float*)d_out);
}

// round 15
// speedup vs baseline: 1.2698x; 1.1936x over previous
#include <cuda_runtime.h>

// CritiGraph_64175401337324 — fused kernel v10:
//  = v7 "decoupled warps" verbatim, except the 16-value merged butterfly is
//    split into two 8-value trees, with butterfly-1 (rows 0-3) executed
//    INSIDE the batch-2 load window to hide its latency.
//  Per-row reduction order identical (xor 16,8,4,2,1) -> eu bit-identical.

namespace {
constexpr int T_   = 1024;
constexpr int S_   = 64;
constexpr int D_   = 256;
constexpr int TP_  = 8;
constexpr int C_   = 65;
constexpr int CUR_TP_ = 4;
}

// pack |v| with sign in bit 31
__device__ __forceinline__ unsigned enc_loc(int v) {
    unsigned a = (unsigned)(v < 0 ? -v : v);
    if (v < 0) a |= 0x80000000u;
    return a;
}

// sign * (16 - e), e = frexp-exponent of ((|a|^|b|)+1). Exact in fp32.
__device__ __forceinline__ float cos_core(unsigned ea, unsigned eb) {
    unsigned u = ea ^ eb;
    int e = 32 - __clz((int)((u & 0x7FFFFFFFu) + 1u));
    float f = (float)(16 - e);
    return (u & 0x80000000u) ? -f : f;
}

__device__ __forceinline__ unsigned bfind_u32(unsigned x) {
    unsigned r;
    asm("bfind.u32 %0, %1;" : "=r"(r) : "r"(x));
    return r;                              // = 31 - clz(x), x != 0
}

// dtype-agnostic int load (LE low word of int32/int64 element)
__device__ __forceinline__ int ld_i(const char* base, int idx, int shf) {
    return *(const int*)(base + ((size_t)idx << shf));
}

// 8-value merged butterfly: reduces {d0..d3, n0..n3} (each a 32-lane sum).
// Returns eu = dot/(sqss*sqrt(nn)). Valid at lanes<16 with
// row = 2*((lane>>3)&1) + ((lane>>2)&1). Per-row order: xor 16,8,4,2,1.
__device__ __forceinline__ float butterfly8(const float* d, const float* n,
                                            int lane, float sqss) {
    float t0[8];
    #pragma unroll
    for (int i = 0; i < 4; ++i) {
        t0[i]     = d[i] + __shfl_xor_sync(0xFFFFFFFFu, d[i], 16);
        t0[i + 4] = n[i] + __shfl_xor_sync(0xFFFFFFFFu, n[i], 16);
    }
    float m4[4];
    #pragma unroll
    for (int k = 0; k < 4; ++k) m4[k] = (lane & 16) ? t0[k + 4] : t0[k];
    float u4[4];
    #pragma unroll
    for (int k = 0; k < 4; ++k)
        u4[k] = m4[k] + __shfl_xor_sync(0xFFFFFFFFu, m4[k], 8);
    float q2[2];
    q2[0] = (lane & 8) ? u4[2] : u4[0];
    q2[1] = (lane & 8) ? u4[3] : u4[1];
    float v2[2];
    #pragma unroll
    for (int k = 0; k < 2; ++k)
        v2[k] = q2[k] + __shfl_xor_sync(0xFFFFFFFFu, q2[k], 4);
    float y = (lane & 4) ? v2[1] : v2[0];
    float x = y + __shfl_xor_sync(0xFFFFFFFFu, y, 2);
    float z = x + __shfl_xor_sync(0xFFFFFFFFu, x, 1);
    float nnv = __shfl_xor_sync(0xFFFFFFFFu, z, 16);
    return z / (sqss * sqrtf(nnv));
}

__global__ void __launch_bounds__(256, 4) fused_kernel(
    const void*  __restrict__ sta_loc,
    const void*  __restrict__ nei_loc,
    const void*  __restrict__ rand_numbers,
    const float* __restrict__ sta_emb,
    const float* __restrict__ nei_emb,
    const float* __restrict__ mask,
    const float* __restrict__ rand_vals,
    const float* __restrict__ t_rand,
    float* __restrict__ out)
{
    const int t    = blockIdx.x;
    const int tid  = threadIdx.x;
    const int lane = tid & 31;
    const int warp = tid >> 5;

    __shared__ __align__(16) unsigned sh_ne[TP_][72];   // warp-private [w][s*9+p]
    __shared__ __align__(16) float    sh_G[TP_][72];
    __shared__ float    sh_w[TP_][TP_];                 // [w][s_local]
    __shared__ float    sh_wb2[TP_][TP_];               // [w][p]
    __shared__ float    sP1[TP_ * 264];                 // [w][j(33)][p]
    __shared__ float    sP2[TP_ * 264];
    __shared__ float    s_loss[C_ * TP_];
    __shared__ float    s_rv[TP_], s_rl[TP_];
    __shared__ int      s_sel;

    // ================= phase A: all loads issued up front =================
    const float4* st4 = (const float4*)(sta_emb + (size_t)t * D_);
    const float4  ua  = st4[lane];
    const float4  ub  = st4[lane + 32];
    const float4* nb  = (const float4*)(nei_emb + ((size_t)(t * S_ + warp * 8)) * D_);

    float4 A[4], Bv[4];
    #pragma unroll
    for (int r = 0; r < 4; ++r) {
        A[r]  = nb[r * 64 + lane];
        Bv[r] = nb[r * 64 + lane + 32];
    }

    // dtype probes (same 64 leading words for every CTA -> cache-hot)
    const long long* pw = (const long long*)sta_loc;
    long long dv0 = pw[lane * 2];
    long long dv1 = pw[lane * 2 + 1];

    // nei_loc slice, speculative both-dtype loads (consecutive int32 pair)
    const int sl = lane >> 2;                // s_local 0..7
    const int p0 = (lane & 3) * 2;           // p pair {p0, p0+1}
    long long nlA = ((const long long*)nei_loc)[(size_t)t * 512 + warp * 64 + lane * 2];
    long long nlB = ((const long long*)nei_loc)[(size_t)t * 512 + warp * 64 + lane * 2 + 1];
    long long nl32 = ((const long long*)nei_loc)[(size_t)t * 256 + warp * 32 + lane];

    // sta_loc pair for (p0, p0+1)
    long long oA  = ((const long long*)sta_loc)[(size_t)t * 8 + p0];
    long long oB  = ((const long long*)sta_loc)[(size_t)t * 8 + p0 + 1];
    long long o32 = ((const long long*)sta_loc)[(size_t)t * 4 + (lane & 3)];

    float m_a   = mask[t * S_ + lane];
    float m_b   = mask[t * S_ + 32 + lane];
    float m_own = mask[t * S_ + warp * 8 + sl];

    if (tid < TP_) s_rv[tid] = rand_vals[t * TP_ + tid];
    if (tid == 0)  s_sel = (t_rand[t] < 0.8f) ? 1 : 0;

    // dtype decision (per warp, no cross-warp sync)
    int is64;
    {
        int lo0 = (int)dv0, hi0 = (int)(dv0 >> 32);
        int lo1 = (int)dv1, hi1 = (int)(dv1 >> 32);
        int ok = (hi0 == (lo0 >> 31)) && (hi1 == (lo1 >> 31));
        is64 = (__ballot_sync(0xFFFFFFFFu, ok) == 0xFFFFFFFFu);
    }
    const int shf = is64 ? 3 : 2;
    const char* RNB = (const char*)rand_numbers + (((size_t)t * 256) << shf);
    const char* SLB = (const char*)sta_loc      + (((size_t)t * 8)   << shf);

    int nl0, nl1, o0, o1;
    if (is64) {
        nl0 = (int)nlA; nl1 = (int)nlB;
        o0  = (int)oA;  o1  = (int)oB;
    } else {
        nl0 = (int)nl32; nl1 = (int)(nl32 >> 32);
        o0  = (int)o32;  o1  = (int)(o32 >> 32);
    }

    // per-warp lth (mask is 0/1: exact in any order)
    float invlth;
    {
        float l = m_a + m_b;
        #pragma unroll
        for (int off = 16; off; off >>= 1) l += __shfl_xor_sync(0xFFFFFFFFu, l, off);
        invlth = __frcp_rn(l + 1e-12f);
    }

    // encode + cos_sn + A8 (warp-local column sums over p)
    float A8_0, A8_1;
    {
        unsigned ne0 = enc_loc(nl0);
        unsigned ne1 = enc_loc(nl1);
        float cs0 = cos_core(enc_loc(o0), ne0) * 0.0625f;   // exact cos
        float cs1 = cos_core(enc_loc(o1), ne1) * 0.0625f;
        float c01 = cs0 + cs1;
        float c2  = c01 + __shfl_xor_sync(0xFFFFFFFFu, c01, 1);
        float sum8 = c2 + __shfl_xor_sync(0xFFFFFFFFu, c2, 2);  // sum over 8 p
        A8_0 = (sum8 - cs0) * 0.125f;
        A8_1 = (sum8 - cs1) * 0.125f;
        sh_ne[warp][sl * 9 + p0]     = ne0;
        sh_ne[warp][sl * 9 + p0 + 1] = ne1;
    }

    // ss reduction early (only needs ua/ub; order xor 16..1 as before)
    float sqss;
    {
        float ss = ua.x*ua.x + ua.y*ua.y + ua.z*ua.z + ua.w*ua.w
                 + ub.x*ub.x + ub.y*ub.y + ub.z*ub.z + ub.w*ub.w;
        #pragma unroll
        for (int off = 16; off; off >>= 1) ss += __shfl_xor_sync(0xFFFFFFFFu, ss, off);
        sqss = sqrtf(ss);
    }

    // ================= eu: B1 dots, B2 loads, butterfly-1 (hides B2) ======
    float dot[8], nn[8];
    #pragma unroll
    for (int r = 0; r < 4; ++r) {
        dot[r] = A[r].x*ua.x + A[r].y*ua.y + A[r].z*ua.z + A[r].w*ua.w
               + Bv[r].x*ub.x + Bv[r].y*ub.y + Bv[r].z*ub.z + Bv[r].w*ub.w;
        nn[r]  = A[r].x*A[r].x + A[r].y*A[r].y + A[r].z*A[r].z + A[r].w*A[r].w
               + Bv[r].x*Bv[r].x + Bv[r].y*Bv[r].y + Bv[r].z*Bv[r].z + Bv[r].w*Bv[r].w;
    }
    #pragma unroll
    for (int r = 0; r < 4; ++r) {            // batch-2 loads in flight...
        A[r]  = nb[(4 + r) * 64 + lane];
        Bv[r] = nb[(4 + r) * 64 + lane + 32];
    }
    // ...while butterfly-1 reduces rows 0-3
    const float euv1 = butterfly8(dot, nn, lane, sqss);

    #pragma unroll
    for (int r = 0; r < 4; ++r) {
        dot[4+r] = A[r].x*ua.x + A[r].y*ua.y + A[r].z*ua.z + A[r].w*ua.w
                 + Bv[r].x*ub.x + Bv[r].y*ub.y + Bv[r].z*ub.z + Bv[r].w*ub.w;
        nn[4+r]  = A[r].x*A[r].x + A[r].y*A[r].y + A[r].z*A[r].z + A[r].w*A[r].w
                 + Bv[r].x*Bv[r].x + Bv[r].y*Bv[r].y + Bv[r].z*Bv[r].z + Bv[r].w*Bv[r].w;
    }
    const float euv2 = butterfly8(dot + 4, nn + 4, lane, sqss);

    // ================= G-prep (warp-local) =================
    {
        // source lane for row r (within its tree): bit3 = r>>1, bit2 = r&1
        int src = (((sl >> 1) & 1) << 3) | ((sl & 1) << 2);
        float e1 = __shfl_sync(0xFFFFFFFFu, euv1, src);
        float e2 = __shfl_sync(0xFFFFFFFFu, euv2, src);
        float eu_s = (sl < 4) ? e1 : e2;
        float w_s  = fabsf(eu_s) * m_own * invlth;
        float B0 = A8_0 - eu_s;
        float B1 = A8_1 - eu_s;
        float q0 = w_s * B0, q1 = w_s * B1;
        sh_G[warp][sl * 9 + p0]     = q0 + q0;     // 2wB (exact x2)
        sh_G[warp][sl * 9 + p0 + 1] = q1 + q1;
        if ((lane & 3) == 0) sh_w[warp][sl] = w_s;
        float wb2_0 = q0 * B0;
        float wb2_1 = q1 * B1;
        #pragma unroll
        for (int off = 4; off <= 16; off <<= 1) {     // sum over 8 s-lanes
            wb2_0 += __shfl_xor_sync(0xFFFFFFFFu, wb2_0, off);
            wb2_1 += __shfl_xor_sync(0xFFFFFFFFu, wb2_1, off);
        }
        if (lane < 4) {
            sh_wb2[warp][2 * lane]     = wb2_0;
            sh_wb2[warp][2 * lane + 1] = wb2_1;
        }
    }
    __syncwarp();

    // ================= phase 4: per-warp partials over own 8 s =============
    {
        const int p  = lane & 7;
        const int jj = lane >> 3;

        unsigned ne_r[8];
        float    G_r[8], w_r[8];
        #pragma unroll
        for (int s = 0; s < 8; ++s) {
            ne_r[s] = sh_ne[warp][s * 9 + p];
            G_r[s]  = sh_G[warp][s * 9 + p];
            w_r[s]  = sh_w[warp][s];
        }
        const float wb2p  = sh_wb2[warp][p];
        const int   ori_p = ld_i(SLB, p, shf);

        int rn_r[8];
        #pragma unroll
        for (int k = 0; k < 8; ++k)
            rn_r[k] = ld_i(RNB, (k * 4 + jj) * 8 + p, shf);
        const unsigned e0_32 = enc_loc(ori_p);

        #pragma unroll
        for (int step = 0; step < 9; ++step) {
            unsigned e0;
            int j;
            if (step < 8) {
                j = step * 4 + jj;
                int h = j >> 1;
                int vc = (ori_p ^ (1 << h)) ^ (rn_r[step] & ((1 << h) - 1));
                e0 = enc_loc(vc);
            } else {
                j = 32;
                e0 = e0_32;
            }
            float P1 = 0.f, P2 = wb2p;
            #pragma unroll
            for (int s = 0; s < 8; ++s) {
                unsigned u  = e0 ^ ne_r[s];
                unsigned x2 = u * 2u + 2u;
                float fc = __uint_as_float(0x4B000000u | bfind_u32(x2));
                float mg = __fmaf_rn(fc, -0.0078125f, 65536.125f);
                float sG = __uint_as_float(__float_as_uint(G_r[s]) ^ (u & 0x80000000u));
                P1 = __fmaf_rn(mg, sG, P1);
                P2 = __fmaf_rn(__fmul_rn(mg, mg), w_r[s], P2);
            }
            if (step < 8 || jj == 0) {
                int base = (warp * 33 + j) * 8 + p;
                sP1[base] = P1;
                sP2[base] = P2;
            }
        }
    }
    __syncthreads();

    // ================= phase 5a: reduce partials over warps ================
    {
        const int j_ = tid >> 3, p_ = tid & 7;
        float S1 = 0.f, S2 = 0.f;
        #pragma unroll
        for (int w = 0; w < 8; ++w) {
            S1 = __fadd_rn(S1, sP1[(w * 33 + j_) * 8 + p_]);
            S2 = __fadd_rn(S2, sP2[(w * 33 + j_) * 8 + p_]);
        }
        // flip bit: candidate value == 0 keeps '+' sign under negation
        int rnv = ld_i(RNB, j_ * 8 + p_, shf);
        int orv = ld_i(SLB, p_, shf);
        int h = j_ >> 1;
        int vc = (orv ^ (1 << h)) ^ (rnv & ((1 << h) - 1));
        unsigned flip = vc ? 0x80000000u : 0u;
        s_loss[j_ * 8 + p_]        = S2 + S1;
        s_loss[(j_ + 33) * 8 + p_] = S2 + __uint_as_float(__float_as_uint(S1) ^ flip);
        if (tid < TP_) {                     // candidate 32
            float T1 = 0.f, T2 = 0.f;
            #pragma unroll
            for (int w = 0; w < 8; ++w) {
                T1 = __fadd_rn(T1, sP1[(w * 33 + 32) * 8 + tid]);
                T2 = __fadd_rn(T2, sP2[(w * 33 + 32) * 8 + tid]);
            }
            s_loss[32 * 8 + tid] = T2 + T1;
        }
    }
    __syncthreads();

    // ================= phase 5b: warp p argmin + outputs ===================
    {
        const int p = warp;
        float va = s_loss[lane * 8 + p];
        float vb = s_loss[(lane + 33) * 8 + p];
        float v = va; int ci = lane;
        if (vb < v) { v = vb; ci = lane + 33; }
        if (lane == 0) {
            float v32 = s_loss[32 * 8 + p];
            if (v32 < v || (v32 == v && 32 < ci)) { v = v32; ci = 32; }
        }
        #pragma unroll
        for (int off = 16; off; off >>= 1) {
            float v2 = __shfl_xor_sync(0xFFFFFFFFu, v, off);
            int   c2 = __shfl_xor_sync(0xFFFFFFFFu, ci, off);
            if (v2 < v || (v2 == v && c2 < ci)) { v = v2; ci = c2; }
        }
        if (lane == 0) {
            float rp = s_rv[p];
            int rank = 0;
            #pragma unroll
            for (int q = 0; q < TP_; ++q)
                rank += (s_rv[q] < rp) || (s_rv[q] == rp && q < p);
            int idx = (rank < CUR_TP_ && s_sel) ? ci : 32;
            int orv = ld_i(SLB, p, shf);
            int vv;
            if (idx == 32) {
                vv = orv;
            } else {
                int c = (idx < 32) ? idx : (idx - 33);
                int rnv = ld_i(RNB, c * 8 + p, shf);
                int h = c >> 1;
                vv = (orv ^ (1 << h)) ^ (rnv & ((1 << h) - 1));
                if (idx >= 33) vv = -vv;
            }
            out[t * TP_ + p] = (float)vv;
            s_rl[p] = s_loss[idx * 8 + p];
        }
    }
    __syncthreads();
    if (tid == 0) {
        float rl = 0.f;
        #pragma unroll
        for (int p = 0; p < TP_; ++p) rl = __fadd_rn(rl, s_rl[p]);
        out[T_ * TP_ + t] = rl * 0.125f;
    }
}

extern "C" void kernel_launch(void* const* d_in, const int* in_sizes, int n_in,
                              void* d_out, int out_size) {
    (void)in_sizes; (void)n_in; (void)out_size;
    fused_kernel<<<T_, 256>>>(
        d_in[0], d_in[1], d_in[2],
        (const float*)d_in[3], (const float*)d_in[4], (const float*)d_in[5],
        (const float*)d_in[6], (const float*)d_in[7],
        (float*)d_out);
}